// round 1
// baseline (speedup 1.0000x reference)
#include <cuda_runtime.h>

#define H_IMG 512
#define W_IMG 512
#define MASK  511
#define PLANE (H_IMG * W_IMG)

#define R_OUT    8                      // output rows per warp
#define WARPS    4
#define COLS_OUT 28                     // valid output cols per warp (lanes 2..29)
#define TILE_ROWS (WARPS * R_OUT)       // 32
#define SM_ROWS  (TILE_ROWS + 14)       // 46  (halo: search 5 + template 2 = 7 each side)
#define SM_COLS  42                     // 28 + 2*7
#define SM_PIX   (SM_ROWS * SM_COLS)    // 1932
#define SMEM_BYTES (SM_PIX * 20)        // float4 x-tile + float y-tile = 38640 B

__global__ __launch_bounds__(32 * WARPS)
void nlm_kernel(const float* __restrict__ x, float* __restrict__ out)
{
    extern __shared__ float smem[];
    float4* xs = (float4*)smem;          // [SM_ROWS][SM_COLS] rgb + pad
    float*  ys = smem + SM_PIX * 4;      // [SM_ROWS][SM_COLS] luminance

    const int lane = threadIdx.x;
    const int warp = threadIdx.y;
    const int tid  = warp * 32 + lane;

    const int n       = blockIdx.z;
    const int rowBase = blockIdx.y * TILE_ROWS;
    const int colBase = blockIdx.x * COLS_OUT;
    const int rowTop  = rowBase - 7 + 512;   // +512 so & MASK is safe
    const int colLeft = colBase - 7 + 512;

    const float* xb = x + (size_t)n * 3 * PLANE;

    // ---- load tile (x channels + luminance), circular wrap ----
    for (int idx = tid; idx < SM_PIX; idx += 32 * WARPS) {
        int r  = idx / SM_COLS;
        int cc = idx - r * SM_COLS;
        int gy = (rowTop + r) & MASK;
        int gx = (colLeft + cc) & MASK;
        const float* p = xb + gy * W_IMG + gx;
        float rv = p[0];
        float gv = p[PLANE];
        float bv = p[2 * PLANE];
        float rc = fminf(fmaxf(rv, 0.f), 1.f);
        float gc = fminf(fmaxf(gv, 0.f), 1.f);
        float bc = fminf(fmaxf(bv, 0.f), 1.f);
        xs[idx] = make_float4(rv, gv, bv, 0.f);
        ys[idx] = 0.299f * rc + 0.587f * gc + 0.114f * bc;
    }
    __syncthreads();

    const int r0 = warp * R_OUT;         // local output-row start of this warp
    const int sc = lane + 5;             // this lane's y column in smem coords

    // own-column luminance in registers (rows r0-2 .. r0+R_OUT+1 in output coords)
    float yreg[R_OUT + 4];
    #pragma unroll
    for (int i = 0; i < R_OUT + 4; ++i)
        yreg[i] = ys[(r0 + 5 + i) * SM_COLS + sc];

    float accW[R_OUT], accR[R_OUT], accG[R_OUT], accB[R_OUT];
    #pragma unroll
    for (int k = 0; k < R_OUT; ++k) { accW[k] = 0.f; accR[k] = 0.f; accG[k] = 0.f; accB[k] = 0.f; }

    const float C_NEG = -1.0f / 3.0f;    // -1/h

    for (int oy = -5; oy <= 5; ++oy) {
        for (int ox = -5; ox <= 5; ++ox) {
            const float*  yp = &ys[(r0 + 5 + oy) * SM_COLS + sc + ox];
            const float4* xp = &xs[(r0 + 7 + oy) * SM_COLS + sc + ox];

            // vertical sliding 5-sum of squared diffs (register ring)
            float ring[5];
            float vs = 0.f;
            #pragma unroll
            for (int i = 0; i < 4; ++i) {
                float d = yreg[i] - yp[i * SM_COLS];
                float s = d * d;
                ring[i] = s;
                vs += s;
            }
            #pragma unroll
            for (int k = 0; k < R_OUT; ++k) {
                const int i = k + 4;
                float d  = yreg[i] - yp[i * SM_COLS];
                float s  = d * d;
                float v5 = vs + s;                 // vsum for output row r0+k, own col
                // horizontal 5-sum across lanes (cols w-2..w+2); lanes 0,1,30,31 are halo
                float a = __shfl_up_sync  (0xffffffffu, v5, 1);
                float b = __shfl_up_sync  (0xffffffffu, v5, 2);
                float c = __shfl_down_sync(0xffffffffu, v5, 1);
                float e = __shfl_down_sync(0xffffffffu, v5, 2);
                float d2 = ((v5 + a) + (b + c)) + e;
                d2 = fmaxf(d2, 1e-12f);            // avoid 0*inf at the center offset
                float dist = d2 * rsqrtf(d2);      // sqrt via MUFU.RSQ
                float wgt  = __expf(dist * C_NEG); // MUFU.EX2
                float4 xv  = xp[k * SM_COLS];      // x(p + offset), rgb
                accW[k] += wgt;
                accR[k] = fmaf(wgt, xv.x, accR[k]);
                accG[k] = fmaf(wgt, xv.y, accG[k]);
                accB[k] = fmaf(wgt, xv.z, accB[k]);
                vs = v5 - ring[k % 5];             // drop leaving row
                ring[(k + 4) % 5] = s;             // keep entering row
            }
        }
    }

    // ---- write output (lanes 2..29 hold valid columns) ----
    if (lane >= 2 && lane < 30) {
        int gc = (colBase + lane - 2) & MASK;
        float* ob = out + (size_t)n * 3 * PLANE;
        #pragma unroll
        for (int k = 0; k < R_OUT; ++k) {
            int gr = rowBase + r0 + k;             // always < 512
            float inv = 1.0f / accW[k];
            float rr = fminf(fmaxf(accR[k] * inv, 0.f), 1.f);
            float gg = fminf(fmaxf(accG[k] * inv, 0.f), 1.f);
            float bb = fminf(fmaxf(accB[k] * inv, 0.f), 1.f);
            ob[             gr * W_IMG + gc] = rr;
            ob[    PLANE +  gr * W_IMG + gc] = gg;
            ob[2 * PLANE +  gr * W_IMG + gc] = bb;
        }
    }
}

extern "C" void kernel_launch(void* const* d_in, const int* in_sizes, int n_in,
                              void* d_out, int out_size)
{
    (void)in_sizes; (void)n_in; (void)out_size;
    const float* x = (const float*)d_in[0];
    float* out = (float*)d_out;

    dim3 block(32, WARPS, 1);
    dim3 grid((W_IMG + COLS_OUT - 1) / COLS_OUT,   // 19 (last tile wraps; duplicate
              H_IMG / TILE_ROWS,                   //     writes are identical values)
              2);
    nlm_kernel<<<grid, block, SMEM_BYTES>>>(x, out);
}

// round 2
// speedup vs baseline: 1.3517x; 1.3517x over previous
#include <cuda_runtime.h>

#define H_IMG 512
#define W_IMG 512
#define MASK  511
#define PLANE (H_IMG * W_IMG)

#define R_OUT    8                      // output rows per warp
#define WARPS    4
#define COLS_OUT 28                     // valid output cols per warp (lanes 2..29)
#define TILE_ROWS (WARPS * R_OUT)       // 32
#define SM_ROWS  (TILE_ROWS + 14)       // 46 (halo 7 each side: search 5 + template 2)
#define SM_COLS  42                     // 28 + 14
#define SM_PIX   (SM_ROWS * SM_COLS)    // 1932
#define FULLM    0xffffffffu

typedef unsigned long long u64;

__device__ __forceinline__ u64 pk(float a, float b) {
    u64 r; asm("mov.b64 %0, {%1, %2};" : "=l"(r) : "f"(a), "f"(b)); return r;
}
__device__ __forceinline__ void up2(u64 v, float& a, float& b) {
    asm("mov.b64 {%0, %1}, %2;" : "=f"(a), "=f"(b) : "l"(v));
}
__device__ __forceinline__ u64 fma2(u64 a, u64 b, u64 c) {
    u64 d; asm("fma.rn.f32x2 %0, %1, %2, %3;" : "=l"(d) : "l"(a), "l"(b), "l"(c)); return d;
}
__device__ __forceinline__ u64 mul2(u64 a, u64 b) {
    u64 d; asm("mul.rn.f32x2 %0, %1, %2;" : "=l"(d) : "l"(a), "l"(b)); return d;
}
__device__ __forceinline__ u64 add2(u64 a, u64 b) {
    u64 d; asm("add.rn.f32x2 %0, %1, %2;" : "=l"(d) : "l"(a), "l"(b)); return d;
}
__device__ __forceinline__ float fsqrt_ap(float x) {
    float r; asm("sqrt.approx.f32 %0, %1;" : "=f"(r) : "f"(x)); return r;
}
__device__ __forceinline__ float fex2(float x) {
    float r; asm("ex2.approx.f32 %0, %1;" : "=f"(r) : "f"(x)); return r;
}

__global__ __launch_bounds__(32 * WARPS, 4)
void nlm_kernel(const float* __restrict__ x, float* __restrict__ out)
{
    __shared__ float smem[4 * SM_PIX];    // y | xr | xg | xb planes, 30912 B
    float* ysm = smem;
    float* xr  = smem + SM_PIX;
    float* xg  = smem + 2 * SM_PIX;
    float* xb  = smem + 3 * SM_PIX;

    const int lane = threadIdx.x;
    const int warp = threadIdx.y;
    const int tid  = warp * 32 + lane;

    const int n       = blockIdx.z;
    const int rowBase = blockIdx.y * TILE_ROWS;
    const int colBase = blockIdx.x * COLS_OUT;
    const int rowTop  = rowBase - 7 + 512;     // +512 so & MASK is safe
    const int colLeft = colBase - 7 + 512;

    const float* xbase = x + (size_t)n * 3 * PLANE;

    // ---- load tile: 3 channel planes + luminance, circular wrap ----
    for (int idx = tid; idx < SM_PIX; idx += 32 * WARPS) {
        int r  = idx / SM_COLS;
        int cc = idx - r * SM_COLS;
        int gy = (rowTop + r) & MASK;
        int gx = (colLeft + cc) & MASK;
        const float* p = xbase + gy * W_IMG + gx;
        float rv = p[0];
        float gv = p[PLANE];
        float bv = p[2 * PLANE];
        float rc = fminf(fmaxf(rv, 0.f), 1.f);
        float gc = fminf(fmaxf(gv, 0.f), 1.f);
        float bc = fminf(fmaxf(bv, 0.f), 1.f);
        xr[idx] = rv;
        xg[idx] = gv;
        xb[idx] = bv;
        ysm[idx] = 0.299f * rc + 0.587f * gc + 0.114f * bc;
    }
    __syncthreads();

    const int r0 = warp * R_OUT;
    const int sc = lane + 5;                   // this lane's column (y coords)

    // own-column luminance, rows r0+5 .. r0+16, packed as 6 f32x2 pairs
    u64 yreg2[6];
    {
        const float* yc = ysm + (r0 + 5) * SM_COLS + sc;
        #pragma unroll
        for (int j = 0; j < 6; ++j)
            yreg2[j] = pk(yc[(2 * j) * SM_COLS], yc[(2 * j + 1) * SM_COLS]);
    }

    u64 accW2[4], accR2[4], accG2[4], accB2[4];
    #pragma unroll
    for (int k2 = 0; k2 < 4; ++k2) {
        accW2[k2] = 0ULL; accR2[k2] = 0ULL; accG2[k2] = 0ULL; accB2[k2] = 0ULL;
    }

    const u64   NEG1 = 0xBF800000BF800000ULL;  // {-1.f, -1.f}
    const float KEXP = -0.4808983469629878f;   // -log2(e)/3

    for (int ox = -5; ox <= 5; ++ox) {
        // shifted y column (rows r0 .. r0+21) into registers, reused for all oy
        float ysh[22];
        {
            const float* yc = ysm + r0 * SM_COLS + sc + ox;
            #pragma unroll
            for (int m = 0; m < 22; ++m) ysh[m] = yc[m * SM_COLS];
        }
        const float* xrB0 = xr + (r0 + 7) * SM_COLS + sc + ox;
        const float* xgB0 = xg + (r0 + 7) * SM_COLS + sc + ox;
        const float* xbB0 = xb + (r0 + 7) * SM_COLS + sc + ox;

        #pragma unroll
        for (int oy = -5; oy <= 5; ++oy) {
            const int base = 5 + oy;

            // squared luminance diffs, rows r0+5..r0+16 (packed pairs)
            float s[12];
            #pragma unroll
            for (int j = 0; j < 6; ++j) {
                u64 yb2 = pk(ysh[2 * j + base], ysh[2 * j + base + 1]);
                u64 df  = fma2(NEG1, yb2, yreg2[j]);     // yreg - ysh
                u64 sq  = mul2(df, df);
                up2(sq, s[2 * j], s[2 * j + 1]);
            }

            // vertical sliding 5-sums
            float v5[8];
            float vs = ((s[0] + s[1]) + (s[2] + s[3])) + s[4];
            v5[0] = vs;
            #pragma unroll
            for (int k = 1; k < 8; ++k) { vs = vs + (s[k + 4] - s[k - 1]); v5[k] = vs; }

            // horizontal 5-sum across lanes (3 shuffles) + weight
            float w[8];
            #pragma unroll
            for (int k = 0; k < 8; ++k) {
                float pr = v5[k] + __shfl_down_sync(FULLM, v5[k], 1);
                float d2 = (__shfl_up_sync(FULLM, pr, 2) + pr)
                         + __shfl_down_sync(FULLM, v5[k], 2);
                w[k] = fex2(fsqrt_ap(d2) * KEXP);        // sqrt(0)=0 -> w=1, no NaN
            }

            // packed accumulation (rows paired)
            const float* xrB = xrB0 + oy * SM_COLS;
            const float* xgB = xgB0 + oy * SM_COLS;
            const float* xbB = xbB0 + oy * SM_COLS;
            #pragma unroll
            for (int k2 = 0; k2 < 4; ++k2) {
                u64 w2 = pk(w[2 * k2], w[2 * k2 + 1]);
                accW2[k2] = add2(accW2[k2], w2);
                accR2[k2] = fma2(w2, pk(xrB[(2 * k2) * SM_COLS], xrB[(2 * k2 + 1) * SM_COLS]), accR2[k2]);
                accG2[k2] = fma2(w2, pk(xgB[(2 * k2) * SM_COLS], xgB[(2 * k2 + 1) * SM_COLS]), accG2[k2]);
                accB2[k2] = fma2(w2, pk(xbB[(2 * k2) * SM_COLS], xbB[(2 * k2 + 1) * SM_COLS]), accB2[k2]);
            }
        }
    }

    // ---- write output (lanes 2..29 hold valid columns) ----
    if (lane >= 2 && lane < 30) {
        int gc = (colBase + lane - 2) & MASK;
        float* ob = out + (size_t)n * 3 * PLANE;
        #pragma unroll
        for (int k2 = 0; k2 < 4; ++k2) {
            float wa, wb, ra, rb, ga, gb, ba, bb;
            up2(accW2[k2], wa, wb);
            up2(accR2[k2], ra, rb);
            up2(accG2[k2], ga, gb);
            up2(accB2[k2], ba, bb);
            int grA = rowBase + r0 + 2 * k2;
            int grB = grA + 1;
            float ia = 1.0f / wa, ib = 1.0f / wb;
            ob[             grA * W_IMG + gc] = fminf(fmaxf(ra * ia, 0.f), 1.f);
            ob[    PLANE +  grA * W_IMG + gc] = fminf(fmaxf(ga * ia, 0.f), 1.f);
            ob[2 * PLANE +  grA * W_IMG + gc] = fminf(fmaxf(ba * ia, 0.f), 1.f);
            ob[             grB * W_IMG + gc] = fminf(fmaxf(rb * ib, 0.f), 1.f);
            ob[    PLANE +  grB * W_IMG + gc] = fminf(fmaxf(gb * ib, 0.f), 1.f);
            ob[2 * PLANE +  grB * W_IMG + gc] = fminf(fmaxf(bb * ib, 0.f), 1.f);
        }
    }
}

extern "C" void kernel_launch(void* const* d_in, const int* in_sizes, int n_in,
                              void* d_out, int out_size)
{
    (void)in_sizes; (void)n_in; (void)out_size;
    const float* x = (const float*)d_in[0];
    float* out = (float*)d_out;

    dim3 block(32, WARPS, 1);
    dim3 grid((W_IMG + COLS_OUT - 1) / COLS_OUT,   // 19 (last tile wraps; duplicate
              H_IMG / TILE_ROWS,                   //     writes are identical values)
              2);
    nlm_kernel<<<grid, block>>>(x, out);
}